// round 15
// baseline (speedup 1.0000x reference)
#include <cuda_runtime.h>

#define NSTEPS 2048
#define D      128
#define NTHR   544   // 16 matrix warps (512 threads) + 1 scalar warp
#define NM     512

typedef unsigned long long u64;

// ---- packed fp32x2 helpers (sm_103a) -------------------------------------
__device__ __forceinline__ u64 ffma2(u64 a, u64 b, u64 c) {
    u64 d; asm("fma.rn.f32x2 %0, %1, %2, %3;" : "=l"(d) : "l"(a), "l"(b), "l"(c));
    return d;
}
__device__ __forceinline__ u64 fmul2(u64 a, u64 b) {
    u64 d; asm("mul.rn.f32x2 %0, %1, %2;" : "=l"(d) : "l"(a), "l"(b));
    return d;
}
__device__ __forceinline__ u64 pack2(float x) {
    u64 r; asm("mov.b64 %0, {%1, %1};" : "=l"(r) : "f"(x));
    return r;
}
__device__ __forceinline__ float hadd2(u64 x) {
    float lo, hi; asm("mov.b64 {%0, %1}, %2;" : "=f"(lo), "=f"(hi) : "l"(x));
    return lo + hi;
}

// Warp-specialized persistent CTA with deferred-J pipelining.
// M-threads (t<512): row r=t>>2, cols [c0,c0+32) of J / SqqSum / SqvSum in regs.
// S-warp (t>=512): scalar recursion (lane 0) + raw dot products (all lanes).
__global__ __launch_bounds__(NTHR, 1)
void gim_kernel(const float* __restrict__ gq,
                const float* __restrict__ gk,
                const float* __restrict__ gv,
                float* __restrict__ out, int out_size)
{
    __shared__ __align__(16) float sq[4][D], sk[4][D], sv[4][D];  // 4-deep ring
    __shared__ __align__(16) float su[2][D], sg[2][D], sw[2][D], sh[2][D];
    __shared__ float swf[2], swi[2];

    const int t   = threadIdx.x;
    const bool isM = (t < NM);
    const int r   = (t >> 2) & 127;
    const int c0  = (t & 3) << 5;

    u64 J2[16], Cqq2[16], Cqv2[16];
    #pragma unroll
    for (int p = 0; p < 16; p++) { J2[p] = 0ull; Cqq2[p] = 0ull; Cqv2[p] = 0ull; }

    // S-warp private state
    float wfp = 1.f, wip = 0.f, vvp = 0.f;
    double Zd = 0.0, Ad = 0.0, Td = 0.0;
    float rd[10];
    #pragma unroll
    for (int p = 0; p < 10; p++) rd[p] = 0.f;

    // pre-load steps 0,1 into ring slots 0,1; zero slot 3 (acts as step -1)
    if (t < 192) {
        const int stp = t / 96, u = t % 96, vec = u >> 5, j = u & 31;
        const float* src = (vec == 0) ? gq : (vec == 1) ? gk : gv;
        float4 x = *(const float4*)&src[stp * D + j * 4];
        float* dst = ((vec == 0) ? sq[stp] : (vec == 1) ? sk[stp] : sv[stp]) + j * 4;
        *(float4*)dst = x;
    } else if (t < 288) {
        const int u = t - 192, vec = u >> 5, j = u & 31;
        float* dst = ((vec == 0) ? sq[3] : (vec == 1) ? sk[3] : sv[3]) + j * 4;
        *(float4*)dst = make_float4(0.f, 0.f, 0.f, 0.f);
    }
    __syncthreads();

    float* outc = out;
    float* outu = (out_size >= 2 * NSTEPS) ? (out + NSTEPS) : (float*)0;

    // iteration i: S finalizes step i; M computes matvecs for step i+1 with
    // J = J_{i-1}; J update for step i happens at the end. i=-1 is the prologue.
    for (int i = -1; i < NSTEPS; i++) {
        if (isM) {
            if (i < NSTEPS - 1) {
                // ---- A1 (step i+1): u' = J q ; Cqq += qq^T ; Cqv += qv^T ;
                //      g = Cqq k ; w = Cqv v     (overlapped with S scalar)
                const int cb = (i + 1) & 3, b = (i + 1) & 1;
                const float* q = sq[cb];
                const float* k = sk[cb];
                const float* v = sv[cb];
                const u64 qr2 = pack2(q[r]);
                u64 pu2 = 0ull, pg2 = 0ull, pw2 = 0ull;
                #pragma unroll
                for (int j = 0; j < 8; j++) {
                    ulonglong2 qc = *(const ulonglong2*)&q[c0 + 4 * j];
                    ulonglong2 vc = *(const ulonglong2*)&v[c0 + 4 * j];
                    ulonglong2 kc = *(const ulonglong2*)&k[c0 + 4 * j];
                    pu2 = ffma2(J2[2*j],   qc.x, pu2);
                    pu2 = ffma2(J2[2*j+1], qc.y, pu2);
                    Cqq2[2*j]   = ffma2(qr2, qc.x, Cqq2[2*j]);
                    Cqq2[2*j+1] = ffma2(qr2, qc.y, Cqq2[2*j+1]);
                    Cqv2[2*j]   = ffma2(qr2, vc.x, Cqv2[2*j]);
                    Cqv2[2*j+1] = ffma2(qr2, vc.y, Cqv2[2*j+1]);
                    pg2 = ffma2(Cqq2[2*j],   kc.x, pg2);
                    pg2 = ffma2(Cqq2[2*j+1], kc.y, pg2);
                    pw2 = ffma2(Cqv2[2*j],   vc.x, pw2);
                    pw2 = ffma2(Cqv2[2*j+1], vc.y, pw2);
                }
                float pu = hadd2(pu2), pg = hadd2(pg2), pw = hadd2(pw2);
                pu += __shfl_xor_sync(~0u, pu, 1); pu += __shfl_xor_sync(~0u, pu, 2);
                pg += __shfl_xor_sync(~0u, pg, 1); pg += __shfl_xor_sync(~0u, pg, 2);
                pw += __shfl_xor_sync(~0u, pw, 1); pw += __shfl_xor_sync(~0u, pw, 2);
                if ((t & 3) == 0) { su[b][r] = pu; sg[b][r] = pg; sw[b][r] = pw; }
            }
        } else if (i >= 0 && (t & 31) == 0) {
            // ---- S scalar for step i (raw dots rd[] from last iteration)
            const float wf = wfp, wi = wip;
            // corrected true dots: u_i = wf*u' + wi*(kL.q)*vL ; etc.
            float nu = wf*wf*rd[0] + 2.f*wf*wi*rd[3]*rd[1] + wi*wi*rd[3]*rd[3]*vvp;
            float vu = wf*rd[2] + wi*rd[3]*rd[4];
            float vh = wf*rd[5] + wi*rd[4]*rd[6];
            float kg = rd[7], kw = rd[8], vv = rd[9];
            double Zc = Zd + (double)vu;           // tr(J SqvS)
            double Ac = Ad + (double)nu;           // tr(J SqqS J^T)
            Td += (double)vv;
            double Pd  = (double)vv * (double)kg;  // l^2 * A_ll
            double vhd = vh, kwd = kw;
            double ni  = Ac * kwd - vhd * Zc;      // sign == sign(margin) == sign(wi)
            float uwf = 1.f, uwi = 0.f, upd = 0.f;
            if (i == 0) { uwf = 0.f; uwi = 1.f; upd = 1.f; }
            else if (ni > 0.0) {
                upd = 1.f;
                double nf  = Pd * Zc - vhd * kwd;
                double den = Ac * Pd - vhd * vhd;
                float rden = __frcp_rn((float)((den == 0.0) ? 1.0 : den));
                float wfv  = (float)nf * rden;
                if (wfv <= 0.f) {
                    uwf = 0.f;
                    uwi = (float)kwd * __frcp_rn((float)((Pd == 0.0) ? 1.0 : Pd));
                } else { uwf = wfv; uwi = (float)ni * rden; }
            }
            const double dwf = uwf, dwi = uwi;
            const double Zn = dwf * Zc + dwi * kwd;
            const double An = dwf*dwf*Ac + 2.0*dwf*dwi*vhd + dwi*dwi*Pd;
            Zd = Zn; Ad = An; wfp = uwf; wip = uwi; vvp = vv;
            outc[i] = (float)(0.5 * Td - Zn + 0.5 * An) * __frcp_rn((float)(i + 1));
            if (outu) outu[i] = upd;
            swf[i & 1] = uwf; swi[i & 1] = uwi;
        }
        __syncthreads();                                   // bar 1

        if (isM && i < NSTEPS - 1) {
            // ---- A2 (step i+1): h' = J g   (J is still J_{i-1})
            const int b = (i + 1) & 1;
            u64 ph2 = 0ull;
            #pragma unroll
            for (int j = 0; j < 8; j++) {
                ulonglong2 gc = *(const ulonglong2*)&sg[b][c0 + 4 * j];
                ph2 = ffma2(J2[2*j],   gc.x, ph2);
                ph2 = ffma2(J2[2*j+1], gc.y, ph2);
            }
            float ph = hadd2(ph2);
            ph += __shfl_xor_sync(~0u, ph, 1); ph += __shfl_xor_sync(~0u, ph, 2);
            if ((t & 3) == 0) sh[b][r] = ph;
        }
        // async prefetch of step i+3 into ring slot (i+3)&3
        if (t < 96) {
            if (i + 3 < NSTEPS) {
                const int vec = t >> 5, j = t & 31, db = (i + 3) & 3;
                const float* src = (vec == 0) ? gq : (vec == 1) ? gk : gv;
                float* dst = ((vec == 0) ? sq[db] : (vec == 1) ? sk[db] : sv[db]) + j * 4;
                unsigned sa = (unsigned)__cvta_generic_to_shared(dst);
                asm volatile("cp.async.ca.shared.global [%0], [%1], 16;"
                             :: "r"(sa), "l"(&src[(i + 3) * D + j * 4]) : "memory");
            }
            asm volatile("cp.async.commit_group;" ::: "memory");
            asm volatile("cp.async.wait_group 1;" ::: "memory");
        }
        __syncthreads();                                   // bar 2

        if (isM) {
            // ---- D (step i): J = wf*J + (wi*v_r)*k^T  (uniform, branchless)
            if (i >= 0) {
                const int vb = i & 3;
                const u64 wf2 = pack2(swf[i & 1]);
                const u64 a2  = pack2(swi[i & 1] * sv[vb][r]);
                const float* k = sk[vb];
                #pragma unroll
                for (int j = 0; j < 8; j++) {
                    ulonglong2 kc = *(const ulonglong2*)&k[c0 + 4 * j];
                    J2[2*j]   = ffma2(wf2, J2[2*j],   fmul2(a2, kc.x));
                    J2[2*j+1] = ffma2(wf2, J2[2*j+1], fmul2(a2, kc.y));
                }
            }
        } else if (i < NSTEPS - 1) {
            // ---- S raw dots for step i+1 (overlapped with M's J update)
            const int b = (i + 1) & 1, cb = (i + 1) & 3, pb = (i + 4) & 3;
            const int e = (t & 31) << 2;
            float4 u4 = *(const float4*)&su[b][e];
            float4 g4 = *(const float4*)&sg[b][e];
            float4 w4 = *(const float4*)&sw[b][e];
            float4 h4 = *(const float4*)&sh[b][e];
            float4 qN = *(const float4*)&sq[cb][e];
            float4 kN = *(const float4*)&sk[cb][e];
            float4 vN = *(const float4*)&sv[cb][e];
            float4 kL = *(const float4*)&sk[pb][e];
            float4 vL = *(const float4*)&sv[pb][e];
            rd[0] = u4.x*u4.x + u4.y*u4.y + u4.z*u4.z + u4.w*u4.w;  // u'.u'
            rd[1] = vL.x*u4.x + vL.y*u4.y + vL.z*u4.z + vL.w*u4.w;  // vL.u'
            rd[2] = vN.x*u4.x + vN.y*u4.y + vN.z*u4.z + vN.w*u4.w;  // vN.u'
            rd[3] = kL.x*qN.x + kL.y*qN.y + kL.z*qN.z + kL.w*qN.w;  // kL.q
            rd[4] = vN.x*vL.x + vN.y*vL.y + vN.z*vL.z + vN.w*vL.w;  // vN.vL
            rd[5] = vN.x*h4.x + vN.y*h4.y + vN.z*h4.z + vN.w*h4.w;  // vN.h'
            rd[6] = kL.x*g4.x + kL.y*g4.y + kL.z*g4.z + kL.w*g4.w;  // kL.g
            rd[7] = kN.x*g4.x + kN.y*g4.y + kN.z*g4.z + kN.w*g4.w;  // k.g
            rd[8] = kN.x*w4.x + kN.y*w4.y + kN.z*w4.z + kN.w*w4.w;  // k.w
            rd[9] = vN.x*vN.x + vN.y*vN.y + vN.z*vN.z + vN.w*vN.w;  // v.v
            #pragma unroll
            for (int o = 16; o >= 1; o >>= 1) {
                #pragma unroll
                for (int p = 0; p < 10; p++)
                    rd[p] += __shfl_xor_sync(~0u, rd[p], o);
            }
        }
        // no third barrier: next A1 reads J (own regs) and ring slots untouched
        // by any post-bar2 writer; S finishes dots before it reaches bar 1.
    }

    // ---- Final: write J (u64 = two adjacent fp32)
    if (isM && out_size >= 2 * NSTEPS + D * D) {
        float* outJ = out + 2 * NSTEPS;
        #pragma unroll
        for (int p = 0; p < 16; p++)
            *(u64*)&outJ[r * D + c0 + 2 * p] = J2[p];
    }
}

extern "C" void kernel_launch(void* const* d_in, const int* in_sizes, int n_in,
                              void* d_out, int out_size)
{
    const float* q = (const float*)d_in[0];
    const float* k = (const float*)d_in[1];
    const float* v = (const float*)d_in[2];
    gim_kernel<<<1, NTHR>>>(q, k, v, (float*)d_out, out_size);
}

// round 16
// speedup vs baseline: 2.4323x; 2.4323x over previous
#include <cuda_runtime.h>

#define NSTEPS 2048
#define D      128
#define NTHR   512
#define VROW   160   // padded vector: 4 chunks x 40 floats (32 data + 8 pad)

typedef unsigned long long u64;

// ---- packed fp32x2 helpers (sm_103a) -------------------------------------
__device__ __forceinline__ u64 ffma2(u64 a, u64 b, u64 c) {
    u64 d; asm("fma.rn.f32x2 %0, %1, %2, %3;" : "=l"(d) : "l"(a), "l"(b), "l"(c));
    return d;
}
__device__ __forceinline__ u64 fmul2(u64 a, u64 b) {
    u64 d; asm("mul.rn.f32x2 %0, %1, %2;" : "=l"(d) : "l"(a), "l"(b));
    return d;
}
__device__ __forceinline__ u64 pack2(float x) {
    u64 r; asm("mov.b64 %0, {%1, %1};" : "=l"(r) : "f"(x));
    return r;
}
__device__ __forceinline__ float hadd2(u64 x) {
    float lo, hi; asm("mov.b64 {%0, %1}, %2;" : "=f"(lo), "=f"(hi) : "l"(x));
    return lo + hi;
}
// logical element c -> padded physical index (chunk stride 40)
__device__ __forceinline__ int padi(int c) { return c + ((c >> 5) << 3); }

// 512-thread persistent CTA, deferred-J pipeline, conflict-free smem layout.
// Thread t: row r=t>>2, cols [32*(t&3), +32) of J / SqqSum / SqvSum in regs.
__global__ __launch_bounds__(NTHR, 1)
void gim_kernel(const float* __restrict__ gq,
                const float* __restrict__ gk,
                const float* __restrict__ gv,
                float* __restrict__ out, int out_size)
{
    __shared__ __align__(16) float sq[4][VROW], sk[4][VROW], sv[4][VROW];
    __shared__ __align__(16) float su[2][VROW], sg[2][VROW], sw[2][VROW], sh[2][VROW];
    __shared__ float swf[2], swi[2];

    const int t   = threadIdx.x;
    const int r   = t >> 2;           // row 0..127
    const int pr  = padi(r);
    const int pc0 = (t & 3) * 40;     // padded chunk base

    u64 J2[16], Cqq2[16], Cqv2[16];
    #pragma unroll
    for (int p = 0; p < 16; p++) { J2[p] = 0ull; Cqq2[p] = 0ull; Cqv2[p] = 0ull; }

    // thread-0 scalar recursion state (held by lane 0 of warp 0)
    float wfp = 1.f, wip = 0.f, vvp = 0.f;
    double Zd = 0.0, Ad = 0.0, Td = 0.0;

    // prologue: load steps 0,1 into ring slots 0,1 ; zero slot 3 (step -1)
    if (t < 192) {
        const int stp = t / 96, u = t % 96, vec = u >> 5, j = u & 31;
        const float* src = (vec == 0) ? gq : (vec == 1) ? gk : gv;
        float4 x = *(const float4*)&src[stp * D + j * 4];
        float* dst = ((vec == 0) ? sq[stp] : (vec == 1) ? sk[stp] : sv[stp]);
        *(float4*)&dst[padi(4 * j)] = x;
    } else if (t < 312) {
        const int u = t - 192, vec = u / 40, jj = u % 40;
        float* dst = (vec == 0) ? sq[3] : (vec == 1) ? sk[3] : sv[3];
        *(float4*)&dst[jj * 4] = make_float4(0.f, 0.f, 0.f, 0.f);
    }
    __syncthreads();

    float* outc = out;
    float* outu = (out_size >= 2 * NSTEPS) ? (out + NSTEPS) : (float*)0;

    // iteration i: A1/A2 compute matvecs for step i+1 with J = J_{i-1};
    // after bar2: all warps apply D(i) (wf/wi from scalar(i), done last iter),
    // warp 0 additionally computes dots(i+1) + scalar(i+1).
    for (int i = -1; i < NSTEPS; i++) {
        if (i < NSTEPS - 1) {
            // ---- A1 (step i+1): u' = J q ; Cqq += qq^T ; Cqv += qv^T ;
            //      g = Cqq k ; w = Cqv v
            const int cb = (i + 1) & 3, b = (i + 1) & 1;
            const float* q = sq[cb];
            const float* k = sk[cb];
            const float* v = sv[cb];
            const u64 qr2 = pack2(q[pr]);
            u64 pu2 = 0ull, pg2 = 0ull, pw2 = 0ull;
            #pragma unroll
            for (int j = 0; j < 8; j++) {
                ulonglong2 qc = *(const ulonglong2*)&q[pc0 + 4 * j];
                ulonglong2 vc = *(const ulonglong2*)&v[pc0 + 4 * j];
                ulonglong2 kc = *(const ulonglong2*)&k[pc0 + 4 * j];
                pu2 = ffma2(J2[2*j],   qc.x, pu2);
                pu2 = ffma2(J2[2*j+1], qc.y, pu2);
                Cqq2[2*j]   = ffma2(qr2, qc.x, Cqq2[2*j]);
                Cqq2[2*j+1] = ffma2(qr2, qc.y, Cqq2[2*j+1]);
                Cqv2[2*j]   = ffma2(qr2, vc.x, Cqv2[2*j]);
                Cqv2[2*j+1] = ffma2(qr2, vc.y, Cqv2[2*j+1]);
                pg2 = ffma2(Cqq2[2*j],   kc.x, pg2);
                pg2 = ffma2(Cqq2[2*j+1], kc.y, pg2);
                pw2 = ffma2(Cqv2[2*j],   vc.x, pw2);
                pw2 = ffma2(Cqv2[2*j+1], vc.y, pw2);
            }
            float pu = hadd2(pu2), pg = hadd2(pg2), pw = hadd2(pw2);
            pu += __shfl_xor_sync(~0u, pu, 1); pu += __shfl_xor_sync(~0u, pu, 2);
            pg += __shfl_xor_sync(~0u, pg, 1); pg += __shfl_xor_sync(~0u, pg, 2);
            pw += __shfl_xor_sync(~0u, pw, 1); pw += __shfl_xor_sync(~0u, pw, 2);
            if ((t & 3) == 0) { su[b][pr] = pu; sg[b][pr] = pg; sw[b][pr] = pw; }
        }
        __syncthreads();                                   // bar 1

        if (i < NSTEPS - 1) {
            // ---- A2 (step i+1): h' = J g   (J still J_{i-1})
            const int b = (i + 1) & 1;
            u64 ph2 = 0ull;
            #pragma unroll
            for (int j = 0; j < 8; j++) {
                ulonglong2 gc = *(const ulonglong2*)&sg[b][pc0 + 4 * j];
                ph2 = ffma2(J2[2*j],   gc.x, ph2);
                ph2 = ffma2(J2[2*j+1], gc.y, ph2);
            }
            float ph = hadd2(ph2);
            ph += __shfl_xor_sync(~0u, ph, 1); ph += __shfl_xor_sync(~0u, ph, 2);
            if ((t & 3) == 0) sh[b][pr] = ph;
        }
        // async prefetch of step i+3 into ring slot (i+3)&3 (warps 13-15)
        if (t >= 416) {
            const int u = t - 416;
            if (i + 3 < NSTEPS) {
                const int vec = u >> 5, j = u & 31, db = (i + 3) & 3;
                const float* src = (vec == 0) ? gq : (vec == 1) ? gk : gv;
                float* dst = ((vec == 0) ? sq[db] : (vec == 1) ? sk[db] : sv[db])
                             + padi(4 * j);
                unsigned sa = (unsigned)__cvta_generic_to_shared(dst);
                asm volatile("cp.async.ca.shared.global [%0], [%1], 16;"
                             :: "r"(sa), "l"(&src[(i + 3) * D + j * 4]) : "memory");
            }
            asm volatile("cp.async.commit_group;" ::: "memory");
            asm volatile("cp.async.wait_group 1;" ::: "memory");
        }
        __syncthreads();                                   // bar 2

        // ---- D (step i): J = wf*J + (wi*v_r)*k^T  (all warps, branchless)
        if (i >= 0) {
            const int vb = i & 3;
            const u64 wf2 = pack2(swf[i & 1]);
            const u64 a2  = pack2(swi[i & 1] * sv[vb][pr]);
            const float* k = sk[vb];
            #pragma unroll
            for (int j = 0; j < 8; j++) {
                ulonglong2 kc = *(const ulonglong2*)&k[pc0 + 4 * j];
                J2[2*j]   = ffma2(wf2, J2[2*j],   fmul2(a2, kc.x));
                J2[2*j+1] = ffma2(wf2, J2[2*j+1], fmul2(a2, kc.y));
            }
        }

        // ---- warp 0: dots(i+1) + scalar(i+1), overlapped with others' D
        if (t < 32 && i < NSTEPS - 1) {
            const int b = (i + 1) & 1, cb = (i + 1) & 3, pb = i & 3;
            const int pe = padi(t << 2);
            float4 u4 = *(const float4*)&su[b][pe];
            float4 g4 = *(const float4*)&sg[b][pe];
            float4 w4 = *(const float4*)&sw[b][pe];
            float4 h4 = *(const float4*)&sh[b][pe];
            float4 qN = *(const float4*)&sq[cb][pe];
            float4 kN = *(const float4*)&sk[cb][pe];
            float4 vN = *(const float4*)&sv[cb][pe];
            float4 kL = *(const float4*)&sk[pb][pe];
            float4 vL = *(const float4*)&sv[pb][pe];
            float rd[10];
            rd[0] = u4.x*u4.x + u4.y*u4.y + u4.z*u4.z + u4.w*u4.w;  // u'.u'
            rd[1] = vL.x*u4.x + vL.y*u4.y + vL.z*u4.z + vL.w*u4.w;  // vL.u'
            rd[2] = vN.x*u4.x + vN.y*u4.y + vN.z*u4.z + vN.w*u4.w;  // vN.u'
            rd[3] = kL.x*qN.x + kL.y*qN.y + kL.z*qN.z + kL.w*qN.w;  // kL.q
            rd[4] = vN.x*vL.x + vN.y*vL.y + vN.z*vL.z + vN.w*vL.w;  // vN.vL
            rd[5] = vN.x*h4.x + vN.y*h4.y + vN.z*h4.z + vN.w*h4.w;  // vN.h'
            rd[6] = kL.x*g4.x + kL.y*g4.y + kL.z*g4.z + kL.w*g4.w;  // kL.g
            rd[7] = kN.x*g4.x + kN.y*g4.y + kN.z*g4.z + kN.w*g4.w;  // k.g
            rd[8] = kN.x*w4.x + kN.y*w4.y + kN.z*w4.z + kN.w*w4.w;  // k.w
            rd[9] = vN.x*vN.x + vN.y*vN.y + vN.z*vN.z + vN.w*vN.w;  // v.v
            #pragma unroll
            for (int o = 16; o >= 1; o >>= 1) {
                #pragma unroll
                for (int p = 0; p < 10; p++)
                    rd[p] += __shfl_xor_sync(~0u, rd[p], o);
            }
            if (t == 0) {
                // corrected true dots for step s=i+1 (J_s-1 = wf*J' + wi*vL kL^T)
                const float wf = wfp, wi = wip;
                float nu = wf*wf*rd[0] + 2.f*wf*wi*rd[3]*rd[1]
                         + wi*wi*rd[3]*rd[3]*vvp;
                float vu = wf*rd[2] + wi*rd[3]*rd[4];
                float vh = wf*rd[5] + wi*rd[4]*rd[6];
                float kg = rd[7], kw = rd[8], vv = rd[9];
                double Zc = Zd + (double)vu;          // tr(J SqvS)
                double Ac = Ad + (double)nu;          // tr(J SqqS J^T)
                Td += (double)vv;
                double Pd  = (double)vv * (double)kg; // l^2 * A_ll
                double vhd = vh, kwd = kw;
                double ni  = Ac * kwd - vhd * Zc;     // sign(margin)==sign(wi)
                float uwf = 1.f, uwi = 0.f, upd = 0.f;
                if (i == -1) { uwf = 0.f; uwi = 1.f; upd = 1.f; }
                else if (ni > 0.0) {
                    upd = 1.f;
                    double nf  = Pd * Zc - vhd * kwd;
                    double den = Ac * Pd - vhd * vhd;
                    float rden = __frcp_rn((float)((den == 0.0) ? 1.0 : den));
                    float wfv  = (float)nf * rden;
                    if (wfv <= 0.f) {
                        uwf = 0.f;
                        uwi = (float)kwd * __frcp_rn((float)((Pd == 0.0) ? 1.0 : Pd));
                    } else { uwf = wfv; uwi = (float)ni * rden; }
                }
                const double dwf = uwf, dwi = uwi;
                const double Zn = dwf * Zc + dwi * kwd;
                const double An = dwf*dwf*Ac + 2.0*dwf*dwi*vhd + dwi*dwi*Pd;
                Zd = Zn; Ad = An; wfp = uwf; wip = uwi; vvp = vv;
                outc[i + 1] = (float)(0.5 * Td - Zn + 0.5 * An)
                            * __frcp_rn((float)(i + 2));
                if (outu) outu[i + 1] = upd;
                swf[(i + 1) & 1] = uwf; swi[(i + 1) & 1] = uwi;
            }
        }
        __syncthreads();                                   // bar 3
    }

    // ---- Final: write J
    if (out_size >= 2 * NSTEPS + D * D) {
        float* outJ = out + 2 * NSTEPS;
        const int c0 = (t & 3) << 5;
        #pragma unroll
        for (int p = 0; p < 16; p++)
            *(u64*)&outJ[r * D + c0 + 2 * p] = J2[p];
    }
}

extern "C" void kernel_launch(void* const* d_in, const int* in_sizes, int n_in,
                              void* d_out, int out_size)
{
    const float* q = (const float*)d_in[0];
    const float* k = (const float*)d_in[1];
    const float* v = (const float*)d_in[2];
    gim_kernel<<<1, NTHR>>>(q, k, v, (float*)d_out, out_size);
}